// round 11
// baseline (speedup 1.0000x reference)
#include <cuda_runtime.h>
#include <math.h>

#define NN 12288
#define EE 196608
#define FF 128

// ---------------- static device scratch ----------------
__device__ int   g_deg[NN];
__device__ int   g_off[NN];
__device__ int   g_cur[NN];
__device__ int   g_src_by_dst[EE];
__device__ int   g_bk_cnt[64];
__device__ int   g_bk_off[64];
__device__ int   g_bk_cur[64];
__device__ int   g_eb_src[EE];
__device__ int   g_eb_dst[EE];
__device__ float g_embed[NN * FF];
__device__ float g_result[NN * 32];
__device__ float g_G[8 * 32 * 32];
__device__ unsigned int g_sumA2;

// ---------------- helpers ----------------
__device__ __forceinline__ float wsum(float v) {
    #pragma unroll
    for (int o = 16; o; o >>= 1) v += __shfl_xor_sync(0xffffffffu, v, o);
    return v;
}
__device__ __forceinline__ float wmax(float v) {
    #pragma unroll
    for (int o = 16; o; o >>= 1) v = fmaxf(v, __shfl_xor_sync(0xffffffffu, v, o));
    return v;
}
__device__ __forceinline__ int lbound(const int* b, int v) {
    int lo = 0, hi = NN;
    while (lo < hi) { int m = (lo + hi) >> 1; if (b[m] < v) lo = m + 1; else hi = m; }
    return lo;
}
__device__ __forceinline__ void ffma2(unsigned long long &c, unsigned long long a,
                                      unsigned long long b) {
    asm("fma.rn.f32x2 %0, %1, %2, %0;" : "+l"(c) : "l"(a), "l"(b));
}
__device__ __forceinline__ unsigned long long pkdup(float a) {
    unsigned long long r;
    asm("mov.b64 %0, {%1, %1};" : "=l"(r) : "f"(a));
    return r;
}
__device__ __forceinline__ float2 upk(unsigned long long v) {
    float2 f;
    asm("mov.b64 {%0, %1}, %2;" : "=f"(f.x), "=f"(f.y) : "l"(v));
    return f;
}

// ---------------- K1: zero init ----------------
__global__ void k_init(float* out) {
    int i = blockIdx.x * 256 + threadIdx.x;
    if (i < 98304) out[i] = 0.f;            // adj_new (65536) + h (32768)
    if (i < NN) g_deg[i] = 0;
    if (i < 64) g_bk_cnt[i] = 0;
    if (i < 8192) g_G[i] = 0.f;
    if (i == 0) g_sumA2 = 0u;
}

// ---------------- K2: histograms (shared-mem aggregated) ----------------
__global__ __launch_bounds__(256) void k_hist(const int* __restrict__ ei,
                                              const int* __restrict__ batch) {
    __shared__ int h[64];
    int t = threadIdx.x;
    if (t < 64) h[t] = 0;
    __syncthreads();
    for (int i = blockIdx.x * 256 + t; i < EE; i += gridDim.x * 256) {
        int s = ei[i], d = ei[EE + i];
        atomicAdd(&g_deg[d], 1);
        atomicAdd(&h[batch[s] * 8 + batch[d]], 1);
    }
    __syncthreads();
    if (t < 64 && h[t]) atomicAdd(&g_bk_cnt[t], h[t]);
}

// ---------------- K3: exclusive scan (shfl-based) ----------------
__global__ void k_scan() {
    __shared__ int wsums[32];
    int t = threadIdx.x, lane = t & 31, w = t >> 5;
    int base = t * 12;
    int loc[12]; int s = 0;
    #pragma unroll
    for (int i = 0; i < 12; i++) { loc[i] = s; s += g_deg[base + i]; }
    int v = s;
    #pragma unroll
    for (int o = 1; o < 32; o <<= 1) {
        int u = __shfl_up_sync(0xffffffffu, v, o);
        if (lane >= o) v += u;
    }
    if (lane == 31) wsums[w] = v;
    __syncthreads();
    if (w == 0) {
        int u = wsums[lane];
        #pragma unroll
        for (int o = 1; o < 32; o <<= 1) {
            int z = __shfl_up_sync(0xffffffffu, u, o);
            if (lane >= o) u += z;
        }
        wsums[lane] = u;
    }
    __syncthreads();
    int pre = (v - s) + (w ? wsums[w - 1] : 0);
    #pragma unroll
    for (int i = 0; i < 12; i++) {
        int o = pre + loc[i];
        g_off[base + i] = o;
        g_cur[base + i] = o;
    }
    if (t == 0) {
        int acc = 0;
        for (int k = 0; k < 64; k++) {
            g_bk_off[k] = acc; g_bk_cur[k] = acc; acc += g_bk_cnt[k];
        }
    }
}

// ---------------- K4: scatter (block-local bucket ranking) ----------------
__global__ __launch_bounds__(1024) void k_scatter(const int* __restrict__ ei,
                                                  const int* __restrict__ batch) {
    __shared__ int cnt[64];
    __shared__ int base[64];
    int t = threadIdx.x;
    if (t < 64) cnt[t] = 0;
    __syncthreads();
    int i = blockIdx.x * 1024 + t;          // EE == 192 * 1024 exactly
    int s = ei[i], d = ei[EE + i];
    int key = batch[s] * 8 + batch[d];
    int rank = atomicAdd(&cnt[key], 1);
    int p = atomicAdd(&g_cur[d], 1);
    g_src_by_dst[p] = s;
    __syncthreads();
    if (t < 64) base[t] = cnt[t] ? atomicAdd(&g_bk_cur[t], cnt[t]) : 0;
    __syncthreads();
    int q = base[key] + rank;
    g_eb_src[q] = s;
    g_eb_dst[q] = d;
}

// ---------------- K5: fused aggregate + GEMM + epilogue ----------------
// 32 rows/block, 256 threads (8 warps); warp w owns rows w*4..w*4+3.
// Unified A smem [256 k][36] = [x | agg] transposed; B double-buffered BK=16
// with register prefetch (LDG of chunk c+1 in flight during compute of c).
#define SM_A   0
#define SM_BS  (256 * 36)
#define SM_TOT (256 * 36 + 2 * 16 * 384)

__global__ __launch_bounds__(256, 2) void k_megemm(
    const float* __restrict__ x,
    const float* __restrict__ Wembd, const float* __restrict__ Wpool,
    const float* __restrict__ bembd, const float* __restrict__ bpool,
    const int* __restrict__ batch)
{
    extern __shared__ float sm[];
    float* A  = sm + SM_A;            // [256][36]
    float* Bs = sm + SM_BS;           // [2][16][384]
    int t = threadIdx.x, lane = t & 31, w = t >> 5;
    int row0 = blockIdx.x * 32;

    // B staging mapping: row rb (0..15), cols cbase+64j (j=0..5)
    int rb = t >> 4, cbase = (t & 15) * 4;
    float4 st[6];
    {   // chunk 0 LDG in flight under the whole gather phase
        const float* we = Wembd + (size_t)rb * 128;
        const float* wp = Wpool + (size_t)rb * 256 - 128;
        st[0] = *(const float4*)(we + cbase);
        st[1] = *(const float4*)(we + cbase + 64);
        st[2] = *(const float4*)(wp + cbase + 128);
        st[3] = *(const float4*)(wp + cbase + 192);
        st[4] = *(const float4*)(wp + cbase + 256);
        st[5] = *(const float4*)(wp + cbase + 320);
    }

    // ---- phase 1a: stage x transposed into A[0..127] ----
    {
        int r = t & 31, bk = (t >> 5) * 16;
        const float* xr = x + (size_t)(row0 + r) * FF + bk;
        #pragma unroll
        for (int i = 0; i < 4; i++) {
            float4 v = *(const float4*)(xr + i * 4);
            A[(bk + i * 4 + 0) * 36 + r] = v.x;
            A[(bk + i * 4 + 1) * 36 + r] = v.y;
            A[(bk + i * 4 + 2) * 36 + r] = v.z;
            A[(bk + i * 4 + 3) * 36 + r] = v.w;
        }
    }

    // ---- phase 1b: mean-aggregate into A[128..255], 4-way unrolled ----
    #pragma unroll
    for (int q = 0; q < 4; q++) {
        int r = w * 4 + q;
        int n = row0 + r;
        int e0 = g_off[n], deg = g_deg[n];
        float4 a0 = make_float4(0.f, 0.f, 0.f, 0.f);
        float4 a1 = a0, a2 = a0, a3 = a0;
        for (int b0 = 0; b0 < deg; b0 += 32) {
            int rem = deg - b0;
            int m = rem < 32 ? rem : 32;
            int idx = (lane < m) ? g_src_by_dst[e0 + b0 + lane] : 0;
            int j = 0;
            for (; j + 4 <= m; j += 4) {
                int s0 = __shfl_sync(0xffffffffu, idx, j);
                int s1 = __shfl_sync(0xffffffffu, idx, j + 1);
                int s2 = __shfl_sync(0xffffffffu, idx, j + 2);
                int s3 = __shfl_sync(0xffffffffu, idx, j + 3);
                float4 v0 = *(const float4*)(x + (size_t)s0 * FF + lane * 4);
                float4 v1 = *(const float4*)(x + (size_t)s1 * FF + lane * 4);
                float4 v2 = *(const float4*)(x + (size_t)s2 * FF + lane * 4);
                float4 v3 = *(const float4*)(x + (size_t)s3 * FF + lane * 4);
                a0.x += v0.x; a0.y += v0.y; a0.z += v0.z; a0.w += v0.w;
                a1.x += v1.x; a1.y += v1.y; a1.z += v1.z; a1.w += v1.w;
                a2.x += v2.x; a2.y += v2.y; a2.z += v2.z; a2.w += v2.w;
                a3.x += v3.x; a3.y += v3.y; a3.z += v3.z; a3.w += v3.w;
            }
            for (; j < m; j++) {
                int sN = __shfl_sync(0xffffffffu, idx, j);
                float4 v = *(const float4*)(x + (size_t)sN * FF + lane * 4);
                a0.x += v.x; a0.y += v.y; a0.z += v.z; a0.w += v.w;
            }
        }
        float inv = 1.f / fmaxf((float)deg, 1.f);
        A[(128 + lane * 4 + 0) * 36 + r] = (a0.x + a1.x + a2.x + a3.x) * inv;
        A[(128 + lane * 4 + 1) * 36 + r] = (a0.y + a1.y + a2.y + a3.y) * inv;
        A[(128 + lane * 4 + 2) * 36 + r] = (a0.z + a1.z + a2.z + a3.z) * inv;
        A[(128 + lane * 4 + 3) * 36 + r] = (a0.w + a1.w + a2.w + a3.w) * inv;
    }

    // store chunk 0 into Bs[0], then one sync makes A + Bs[0] visible
    {
        float* brow = Bs + rb * 384;
        #pragma unroll
        for (int j = 0; j < 6; j++)
            *(float4*)(brow + cbase + 64 * j) = st[j];
    }
    __syncthreads();

    // ---- phase 2: pipelined GEMM, 16 chunks of BK=16, 1 sync/chunk ----
    unsigned long long acc[4][3][2];
    #pragma unroll
    for (int r = 0; r < 4; r++)
        #pragma unroll
        for (int c = 0; c < 3; c++) { acc[r][c][0] = 0ull; acc[r][c][1] = 0ull; }

    for (int c = 0; c < 16; c++) {
        int buf = c & 1;
        if (c + 1 < 16) {   // prefetch chunk c+1 into registers
            const float* we = Wembd + (size_t)(16 * (c + 1) + rb) * 128;
            const float* wp = Wpool + (size_t)(16 * (c + 1) + rb) * 256 - 128;
            st[0] = *(const float4*)(we + cbase);
            st[1] = *(const float4*)(we + cbase + 64);
            st[2] = *(const float4*)(wp + cbase + 128);
            st[3] = *(const float4*)(wp + cbase + 192);
            st[4] = *(const float4*)(wp + cbase + 256);
            st[5] = *(const float4*)(wp + cbase + 320);
        }
        const float* Abase = A + (size_t)c * 16 * 36;
        const float* Bbase = Bs + (size_t)buf * 16 * 384;
        #pragma unroll
        for (int k = 0; k < 16; k++) {
            float4 a4 = *(const float4*)(Abase + k * 36 + w * 4); // warp-broadcast
            unsigned long long a0 = pkdup(a4.x), a1 = pkdup(a4.y);
            unsigned long long a2 = pkdup(a4.z), a3 = pkdup(a4.w);
            #pragma unroll
            for (int cc = 0; cc < 3; cc++) {
                ulonglong2 b = *(const ulonglong2*)(Bbase + k * 384 + cc * 128 + lane * 4);
                ffma2(acc[0][cc][0], a0, b.x); ffma2(acc[0][cc][1], a0, b.y);
                ffma2(acc[1][cc][0], a1, b.x); ffma2(acc[1][cc][1], a1, b.y);
                ffma2(acc[2][cc][0], a2, b.x); ffma2(acc[2][cc][1], a2, b.y);
                ffma2(acc[3][cc][0], a3, b.x); ffma2(acc[3][cc][1], a3, b.y);
            }
        }
        if (c + 1 < 16) {   // write prefetched chunk into the other buffer
            float* brow = Bs + (size_t)(buf ^ 1) * 16 * 384 + rb * 384;
            #pragma unroll
            for (int j = 0; j < 6; j++)
                *(float4*)(brow + cbase + 64 * j) = st[j];
        }
        __syncthreads();
    }

    // ---- phase 3: epilogue (bias, norms, block softmax) ----
    float4 be  = *(const float4*)(bembd + lane * 4);
    float4 bp0 = *(const float4*)(bpool + lane * 4);
    float4 bp1 = *(const float4*)(bpool + 128 + lane * 4);
    #pragma unroll
    for (int r = 0; r < 4; r++) {
        int n = row0 + w * 4 + r;
        int g = batch[n];
        float2 e0 = upk(acc[r][0][0]), e1 = upk(acc[r][0][1]);
        float4 v = make_float4(e0.x + be.x, e0.y + be.y, e1.x + be.z, e1.y + be.w);
        float ss = wsum(v.x * v.x + v.y * v.y + v.z * v.z + v.w * v.w);
        float inv = 1.f / fmaxf(sqrtf(ss), 1e-12f);
        *(float4*)(g_embed + (size_t)n * FF + lane * 4) =
            make_float4(v.x * inv, v.y * inv, v.z * inv, v.w * inv);

        float2 q0 = upk(acc[r][1][0]), q1 = upk(acc[r][1][1]);
        float2 q2 = upk(acc[r][2][0]), q3 = upk(acc[r][2][1]);
        float4 P0 = make_float4(q0.x + bp0.x, q0.y + bp0.y, q1.x + bp0.z, q1.y + bp0.w);
        float4 P1 = make_float4(q2.x + bp1.x, q2.y + bp1.y, q3.x + bp1.z, q3.y + bp1.w);
        float ss2 = wsum(P0.x * P0.x + P0.y * P0.y + P0.z * P0.z + P0.w * P0.w +
                         P1.x * P1.x + P1.y * P1.y + P1.z * P1.z + P1.w * P1.w);
        float inv2 = 1.f / fmaxf(sqrtf(ss2), 1e-12f);

        float4 M = (g < 4) ? P0 : P1;
        bool own = (lane >> 3) == (g & 3);
        float m0 = M.x * inv2, m1 = M.y * inv2, m2 = M.z * inv2, m3 = M.w * inv2;
        float loc = own ? fmaxf(fmaxf(m0, m1), fmaxf(m2, m3)) : -1e30f;
        float mx = wmax(loc);
        float ex0 = 0.f, ex1 = 0.f, ex2 = 0.f, ex3 = 0.f;
        if (own) {
            ex0 = __expf(m0 - mx); ex1 = __expf(m1 - mx);
            ex2 = __expf(m2 - mx); ex3 = __expf(m3 - mx);
        }
        float s = wsum(ex0 + ex1 + ex2 + ex3);
        if (own) {
            float is = 1.f / s;
            *(float4*)(g_result + (size_t)n * 32 + (lane & 7) * 4) =
                make_float4(ex0 * is, ex1 * is, ex2 * is, ex3 * is);
        }
    }
}

// ---------------- K6: merged post (adj 512 | pool 128 | dup 48 blocks) -------
__global__ __launch_bounds__(256) void k_post(const int* __restrict__ batch, float* out) {
    __shared__ float shf[640];
    __shared__ int srange[2];
    int b = blockIdx.x;
    int t = threadIdx.x;

    if (b < 512) {
        // ---- adj_new = sum_edges outer(S[src], S[dst]) ----
        int bk = b & 63, split = b >> 6;
        int s0 = g_bk_off[bk];
        int s1 = (bk == 63) ? EE : g_bk_off[bk + 1];
        int len = s1 - s0;
        int per = (len + 7) / 8;
        int e0 = s0 + split * per;
        int e1 = min(e0 + per, s1);
        float (*Sa)[32] = (float(*)[32])shf;
        float (*Sb)[32] = (float(*)[32])(shf + 256);
        int i = t >> 3, j0 = (t & 7) * 4;
        float4 acc = make_float4(0.f, 0.f, 0.f, 0.f);
        for (int base = e0; base < e1; base += 8) {
            int ne = min(8, e1 - base);
            if ((t >> 5) < ne) {
                int e = base + (t >> 5);
                int l = t & 31;
                Sa[t >> 5][l] = g_result[(size_t)g_eb_src[e] * 32 + l];
                Sb[t >> 5][l] = g_result[(size_t)g_eb_dst[e] * 32 + l];
            }
            __syncthreads();
            for (int jj = 0; jj < ne; jj++) {
                float a = Sa[jj][i];
                float4 bv = *(const float4*)&Sb[jj][j0];
                acc.x += a * bv.x; acc.y += a * bv.y;
                acc.z += a * bv.z; acc.w += a * bv.w;
            }
            __syncthreads();
        }
        if (e0 < e1) {
            int gs = bk >> 3, gd = bk & 7;
            float* dst = out + (size_t)(gs * 32 + i) * 256 + gd * 32 + j0;
            atomicAdd(dst + 0, acc.x); atomicAdd(dst + 1, acc.y);
            atomicAdd(dst + 2, acc.z); atomicAdd(dst + 3, acc.w);
        }
    } else if (b < 640) {
        // ---- h = S^T E and G = S^T S (per graph) ----
        int pb = b - 512;
        int g = pb & 7, split = pb >> 3;
        float (*Ms)[160] = (float(*)[160])shf;
        if (t == 0) { srange[0] = lbound(batch, g); srange[1] = lbound(batch, g + 1); }
        __syncthreads();
        int n0 = srange[0], n1 = srange[1];
        int len = n1 - n0;
        int per = (len + 15) / 16;
        int m0 = n0 + split * per;
        int m1 = min(m0 + per, n1);
        int i = t >> 3, j0 = (t & 7) * 4;
        float4 acc[5];
        #pragma unroll
        for (int c = 0; c < 5; c++) acc[c] = make_float4(0.f, 0.f, 0.f, 0.f);
        for (int base = m0; base < m1; base += 4) {
            int nn = min(4, m1 - base);
            for (int idx = t; idx < nn * 160; idx += 256) {
                int j = idx / 160, c = idx % 160;
                int n = base + j;
                Ms[j][c] = (c < 128) ? g_embed[(size_t)n * 128 + c]
                                     : g_result[(size_t)n * 32 + (c - 128)];
            }
            __syncthreads();
            for (int jj = 0; jj < nn; jj++) {
                float a = Ms[jj][128 + i];
                #pragma unroll
                for (int c = 0; c < 5; c++) {
                    float4 v = *(const float4*)&Ms[jj][j0 + 32 * c];
                    acc[c].x += a * v.x; acc[c].y += a * v.y;
                    acc[c].z += a * v.z; acc[c].w += a * v.w;
                }
            }
            __syncthreads();
        }
        if (m0 < m1) {
            #pragma unroll
            for (int c = 0; c < 4; c++) {
                float* dst = out + 65536 + (size_t)(g * 32 + i) * 128 + j0 + 32 * c;
                atomicAdd(dst + 0, acc[c].x); atomicAdd(dst + 1, acc[c].y);
                atomicAdd(dst + 2, acc[c].z); atomicAdd(dst + 3, acc[c].w);
            }
            float* dg = g_G + (size_t)g * 1024 + i * 32 + j0;
            atomicAdd(dg + 0, acc[4].x); atomicAdd(dg + 1, acc[4].y);
            atomicAdd(dg + 2, acc[4].z); atomicAdd(dg + 3, acc[4].w);
        }
    } else {
        // ---- sum of squared edge multiplicities (exact, int) ----
        int n = (b - 640) * 256 + t;
        int cnt = 0;
        if (n < NN) {
            int o = g_off[n], L = g_deg[n];
            for (int ii = 0; ii < L; ii++) {
                int si = g_src_by_dst[o + ii];
                for (int jj = 0; jj < L; jj++) cnt += (g_src_by_dst[o + jj] == si);
            }
        }
        #pragma unroll
        for (int off = 16; off; off >>= 1) cnt += __shfl_xor_sync(0xffffffffu, cnt, off);
        if ((t & 31) == 0) atomicAdd(&g_sumA2, (unsigned int)cnt);
    }
}

// ---------------- K7: finalize losses ----------------
__global__ void k_final(float* out) {
    __shared__ float red[256];
    int t = threadIdx.x;
    float v = out[(size_t)t * 257];          // trace(adj_new)
    red[t] = v;
    __syncthreads();
    for (int s = 128; s; s >>= 1) { if (t < s) red[t] += red[t + s]; __syncthreads(); }
    float tr = red[0];
    __syncthreads();
    float gq = 0.f;                          // ||G||_F^2
    for (int i = t; i < 8192; i += 256) { float g = g_G[i]; gq += g * g; }
    red[t] = gq;
    __syncthreads();
    for (int s = 128; s; s >>= 1) { if (t < s) red[t] += red[t + s]; __syncthreads(); }
    if (t == 0) {
        float a2 = (float)g_sumA2;
        float val = a2 - 2.f * tr + red[0];
        out[98304] = sqrtf(fmaxf(val, 0.f)) / 150994944.0f;   // / N^2
        out[98305] = 12288.0f * logf(32.0f);
    }
}

// ---------------- launch ----------------
extern "C" void kernel_launch(void* const* d_in, const int* in_sizes, int n_in,
                              void* d_out, int out_size) {
    const float* x     = (const float*)d_in[0];
    const int*   ei    = (const int*)d_in[1];
    const int*   batch = (const int*)d_in[2];
    const float* Wembd = (const float*)d_in[3];
    const float* bembd = (const float*)d_in[4];
    const float* Wpool = (const float*)d_in[5];
    const float* bpool = (const float*)d_in[6];
    float* out = (float*)d_out;

    static_assert(SM_TOT * 4 == 86016, "smem layout");
    cudaFuncSetAttribute(k_megemm, cudaFuncAttributeMaxDynamicSharedMemorySize,
                         SM_TOT * 4);

    k_init<<<384, 256>>>(out);
    k_hist<<<96, 256>>>(ei, batch);
    k_scan<<<1, 1024>>>();
    k_scatter<<<192, 1024>>>(ei, batch);
    k_megemm<<<384, 256, SM_TOT * 4>>>(x, Wembd, Wpool, bembd, bpool, batch);
    k_post<<<688, 256>>>(batch, out);
    k_final<<<1, 256>>>(out);
}

// round 12
// speedup vs baseline: 1.4567x; 1.4567x over previous
#include <cuda_runtime.h>
#include <math.h>

#define NN 12288
#define EE 196608
#define FF 128

// ---------------- static device scratch ----------------
__device__ int   g_deg[NN];
__device__ int   g_off[NN];
__device__ int   g_cur[NN];
__device__ int   g_src_by_dst[EE];
__device__ int   g_bk_cnt[64];
__device__ int   g_bk_off[64];
__device__ int   g_bk_cur[64];
__device__ int   g_eb_src[EE];
__device__ int   g_eb_dst[EE];
__device__ float g_embed[NN * FF];
__device__ float g_result[NN * 32];
__device__ float g_G[8 * 32 * 32];
__device__ unsigned int g_sumA2;

// ---------------- helpers ----------------
__device__ __forceinline__ float wsum(float v) {
    #pragma unroll
    for (int o = 16; o; o >>= 1) v += __shfl_xor_sync(0xffffffffu, v, o);
    return v;
}
__device__ __forceinline__ float wmax(float v) {
    #pragma unroll
    for (int o = 16; o; o >>= 1) v = fmaxf(v, __shfl_xor_sync(0xffffffffu, v, o));
    return v;
}
__device__ __forceinline__ int lbound(const int* b, int v) {
    int lo = 0, hi = NN;
    while (lo < hi) { int m = (lo + hi) >> 1; if (b[m] < v) lo = m + 1; else hi = m; }
    return lo;
}
__device__ __forceinline__ void ffma2(unsigned long long &c, unsigned long long a,
                                      unsigned long long b) {
    asm("fma.rn.f32x2 %0, %1, %2, %0;" : "+l"(c) : "l"(a), "l"(b));
}
__device__ __forceinline__ unsigned long long pkdup(float a) {
    unsigned long long r;
    asm("mov.b64 %0, {%1, %1};" : "=l"(r) : "f"(a));
    return r;
}

// ---------------- K1: zero init ----------------
__global__ void k_init(float* out) {
    int i = blockIdx.x * 256 + threadIdx.x;
    if (i < 98304) out[i] = 0.f;            // adj_new (65536) + h (32768)
    if (i < NN) g_deg[i] = 0;
    if (i < 64) g_bk_cnt[i] = 0;
    if (i < 8192) g_G[i] = 0.f;
    if (i == 0) g_sumA2 = 0u;
}

// ---------------- K2: histograms (shared-mem aggregated) ----------------
__global__ __launch_bounds__(256) void k_hist(const int* __restrict__ ei,
                                              const int* __restrict__ batch) {
    __shared__ int h[64];
    int t = threadIdx.x;
    if (t < 64) h[t] = 0;
    __syncthreads();
    for (int i = blockIdx.x * 256 + t; i < EE; i += gridDim.x * 256) {
        int s = ei[i], d = ei[EE + i];
        atomicAdd(&g_deg[d], 1);
        atomicAdd(&h[batch[s] * 8 + batch[d]], 1);
    }
    __syncthreads();
    if (t < 64 && h[t]) atomicAdd(&g_bk_cnt[t], h[t]);
}

// ---------------- K3: exclusive scan (shfl-based) ----------------
__global__ void k_scan() {
    __shared__ int wsums[32];
    int t = threadIdx.x, lane = t & 31, w = t >> 5;
    int base = t * 12;
    int loc[12]; int s = 0;
    #pragma unroll
    for (int i = 0; i < 12; i++) { loc[i] = s; s += g_deg[base + i]; }
    int v = s;
    #pragma unroll
    for (int o = 1; o < 32; o <<= 1) {
        int u = __shfl_up_sync(0xffffffffu, v, o);
        if (lane >= o) v += u;
    }
    if (lane == 31) wsums[w] = v;
    __syncthreads();
    if (w == 0) {
        int u = wsums[lane];
        #pragma unroll
        for (int o = 1; o < 32; o <<= 1) {
            int z = __shfl_up_sync(0xffffffffu, u, o);
            if (lane >= o) u += z;
        }
        wsums[lane] = u;
    }
    __syncthreads();
    int pre = (v - s) + (w ? wsums[w - 1] : 0);
    #pragma unroll
    for (int i = 0; i < 12; i++) {
        int o = pre + loc[i];
        g_off[base + i] = o;
        g_cur[base + i] = o;
    }
    if (t == 0) {
        int acc = 0;
        for (int k = 0; k < 64; k++) {
            g_bk_off[k] = acc; g_bk_cur[k] = acc; acc += g_bk_cnt[k];
        }
    }
}

// ---------------- K4: scatter (block-local bucket ranking) ----------------
__global__ __launch_bounds__(1024) void k_scatter(const int* __restrict__ ei,
                                                  const int* __restrict__ batch) {
    __shared__ int cnt[64];
    __shared__ int base[64];
    int t = threadIdx.x;
    if (t < 64) cnt[t] = 0;
    __syncthreads();
    int i = blockIdx.x * 1024 + t;          // EE == 192 * 1024 exactly
    int s = ei[i], d = ei[EE + i];
    int key = batch[s] * 8 + batch[d];
    int rank = atomicAdd(&cnt[key], 1);
    int p = atomicAdd(&g_cur[d], 1);
    g_src_by_dst[p] = s;
    __syncthreads();
    if (t < 64) base[t] = cnt[t] ? atomicAdd(&g_bk_cur[t], cnt[t]) : 0;
    __syncthreads();
    int q = base[key] + rank;
    g_eb_src[q] = s;
    g_eb_dst[q] = d;
}

// ---------------- K5: fused aggregate + GEMM + epilogue (BK=32, col-split) ---
// 32 rows/block, 256 threads (8 warps).
// GEMM: warp w owns cols [48w,48w+48); lane: rg=lane>>2 -> rows 4rg..4rg+3,
//       cg=lane&3 -> 12 cols. 8x less smem B traffic than row-split.
// smem layout (floats): aggT[128*36] | As[32*36] | Bs[32*384]
#define SM_AGGT 0
#define SM_AS   (128 * 36)
#define SM_BS   (128 * 36 + 32 * 36)
#define SM_TOT  (128 * 36 + 32 * 36 + 32 * 384)

__global__ __launch_bounds__(256, 2) void k_megemm(
    const float* __restrict__ x,
    const float* __restrict__ Wembd, const float* __restrict__ Wpool,
    const float* __restrict__ bembd, const float* __restrict__ bpool,
    const int* __restrict__ batch)
{
    extern __shared__ float sm[];
    float* aggT = sm + SM_AGGT;   // [128][36] transposed agg
    float* As   = sm + SM_AS;     // [32][36] transposed x chunk
    float* Bs   = sm + SM_BS;     // [32][384] weight chunk (reused as out tile)
    int t = threadIdx.x, lane = t & 31, w = t >> 5;
    int row0 = blockIdx.x * 32;

    // ---- phase 1: mean-aggregate, 4-way unrolled (MLP>=4) ----
    #pragma unroll
    for (int q = 0; q < 4; q++) {
        int r = w * 4 + q;
        int n = row0 + r;
        int e0 = g_off[n], deg = g_deg[n];
        float4 a0 = make_float4(0.f, 0.f, 0.f, 0.f);
        float4 a1 = a0, a2 = a0, a3 = a0;
        for (int b0 = 0; b0 < deg; b0 += 32) {
            int rem = deg - b0;
            int m = rem < 32 ? rem : 32;
            int idx = (lane < m) ? g_src_by_dst[e0 + b0 + lane] : 0;
            int j = 0;
            for (; j + 4 <= m; j += 4) {
                int s0 = __shfl_sync(0xffffffffu, idx, j);
                int s1 = __shfl_sync(0xffffffffu, idx, j + 1);
                int s2 = __shfl_sync(0xffffffffu, idx, j + 2);
                int s3 = __shfl_sync(0xffffffffu, idx, j + 3);
                float4 v0 = *(const float4*)(x + (size_t)s0 * FF + lane * 4);
                float4 v1 = *(const float4*)(x + (size_t)s1 * FF + lane * 4);
                float4 v2 = *(const float4*)(x + (size_t)s2 * FF + lane * 4);
                float4 v3 = *(const float4*)(x + (size_t)s3 * FF + lane * 4);
                a0.x += v0.x; a0.y += v0.y; a0.z += v0.z; a0.w += v0.w;
                a1.x += v1.x; a1.y += v1.y; a1.z += v1.z; a1.w += v1.w;
                a2.x += v2.x; a2.y += v2.y; a2.z += v2.z; a2.w += v2.w;
                a3.x += v3.x; a3.y += v3.y; a3.z += v3.z; a3.w += v3.w;
            }
            for (; j < m; j++) {
                int sN = __shfl_sync(0xffffffffu, idx, j);
                float4 v = *(const float4*)(x + (size_t)sN * FF + lane * 4);
                a0.x += v.x; a0.y += v.y; a0.z += v.z; a0.w += v.w;
            }
        }
        float inv = 1.f / fmaxf((float)deg, 1.f);
        aggT[(lane * 4 + 0) * 36 + r] = (a0.x + a1.x + a2.x + a3.x) * inv;
        aggT[(lane * 4 + 1) * 36 + r] = (a0.y + a1.y + a2.y + a3.y) * inv;
        aggT[(lane * 4 + 2) * 36 + r] = (a0.z + a1.z + a2.z + a3.z) * inv;
        aggT[(lane * 4 + 3) * 36 + r] = (a0.w + a1.w + a2.w + a3.w) * inv;
    }
    __syncthreads();

    // ---- phase 2: GEMM, 8 chunks of BK=32, column-split warp tiling ----
    int rg = lane >> 2;                     // row group: rows 4rg..4rg+3
    int cb = 48 * w + 12 * (lane & 3);      // this lane's 12 columns
    unsigned long long acc[4][6];
    #pragma unroll
    for (int i = 0; i < 4; i++)
        #pragma unroll
        for (int j = 0; j < 6; j++) acc[i][j] = 0ull;

    int rb = t >> 3, c0 = (t & 7) * 4;      // B staging: row rb, cols c0+32j
    int r_a = t & 31, kq_a = (t >> 5) * 4;  // x staging mapping

    for (int c = 0; c < 8; c++) {
        int kc = c * 32;
        if (c) __syncthreads();             // prior compute done reading Bs/As
        {   // stage B chunk: 32 rows x 384 cols, interleaved 32-float strides
            const float* we = Wembd + (size_t)(kc + rb) * 128;
            const float* wp = Wpool + (size_t)(kc + rb) * 256 - 128;
            float* brow = Bs + rb * 384;
            #pragma unroll
            for (int j = 0; j < 12; j++) {
                int col = c0 + 32 * j;
                float4 v = (col < 128) ? *(const float4*)(we + col)
                                       : *(const float4*)(wp + col);
                *(float4*)(brow + col) = v;
            }
        }
        if (c < 4) {                        // stage x chunk transposed
            float4 v = *(const float4*)(x + (size_t)(row0 + r_a) * FF + kc + kq_a);
            As[(kq_a + 0) * 36 + r_a] = v.x;
            As[(kq_a + 1) * 36 + r_a] = v.y;
            As[(kq_a + 2) * 36 + r_a] = v.z;
            As[(kq_a + 3) * 36 + r_a] = v.w;
        }
        __syncthreads();
        const float* Abase = (c < 4) ? As : (aggT + (size_t)32 * (c - 4) * 36);
        #pragma unroll
        for (int k = 0; k < 32; k++) {
            float4 a4 = *(const float4*)(Abase + k * 36 + rg * 4);
            unsigned long long a0 = pkdup(a4.x), a1 = pkdup(a4.y);
            unsigned long long a2 = pkdup(a4.z), a3 = pkdup(a4.w);
            const float* bp = Bs + k * 384 + cb;
            ulonglong2 b01 = *(const ulonglong2*)(bp);
            ulonglong2 b23 = *(const ulonglong2*)(bp + 4);
            ulonglong2 b45 = *(const ulonglong2*)(bp + 8);
            ffma2(acc[0][0], a0, b01.x); ffma2(acc[0][1], a0, b01.y);
            ffma2(acc[0][2], a0, b23.x); ffma2(acc[0][3], a0, b23.y);
            ffma2(acc[0][4], a0, b45.x); ffma2(acc[0][5], a0, b45.y);
            ffma2(acc[1][0], a1, b01.x); ffma2(acc[1][1], a1, b01.y);
            ffma2(acc[1][2], a1, b23.x); ffma2(acc[1][3], a1, b23.y);
            ffma2(acc[1][4], a1, b45.x); ffma2(acc[1][5], a1, b45.y);
            ffma2(acc[2][0], a2, b01.x); ffma2(acc[2][1], a2, b01.y);
            ffma2(acc[2][2], a2, b23.x); ffma2(acc[2][3], a2, b23.y);
            ffma2(acc[2][4], a2, b45.x); ffma2(acc[2][5], a2, b45.y);
            ffma2(acc[3][0], a3, b01.x); ffma2(acc[3][1], a3, b01.y);
            ffma2(acc[3][2], a3, b23.x); ffma2(acc[3][3], a3, b23.y);
            ffma2(acc[3][4], a3, b45.x); ffma2(acc[3][5], a3, b45.y);
        }
    }

    // ---- phase 2b: dump output tile into smem (reuse Bs as [32][384]) ----
    __syncthreads();
    float* So = Bs;
    #pragma unroll
    for (int i = 0; i < 4; i++)
        #pragma unroll
        for (int j = 0; j < 6; j++)
            *(unsigned long long*)(So + (size_t)(rg * 4 + i) * 384 + cb + 2 * j)
                = acc[i][j];
    __syncthreads();

    // ---- phase 3: epilogue (bias, norms, block softmax) ----
    float4 be  = *(const float4*)(bembd + lane * 4);
    float4 bp0 = *(const float4*)(bpool + lane * 4);
    float4 bp1 = *(const float4*)(bpool + 128 + lane * 4);
    #pragma unroll
    for (int r = 0; r < 4; r++) {
        int rl = w * 4 + r;
        int n = row0 + rl;
        int g = batch[n];
        const float* Sr = So + (size_t)rl * 384;
        float4 v = *(const float4*)(Sr + lane * 4);
        v.x += be.x; v.y += be.y; v.z += be.z; v.w += be.w;
        float ss = wsum(v.x * v.x + v.y * v.y + v.z * v.z + v.w * v.w);
        float inv = 1.f / fmaxf(sqrtf(ss), 1e-12f);
        *(float4*)(g_embed + (size_t)n * FF + lane * 4) =
            make_float4(v.x * inv, v.y * inv, v.z * inv, v.w * inv);

        float4 P0 = *(const float4*)(Sr + 128 + lane * 4);
        float4 P1 = *(const float4*)(Sr + 256 + lane * 4);
        P0.x += bp0.x; P0.y += bp0.y; P0.z += bp0.z; P0.w += bp0.w;
        P1.x += bp1.x; P1.y += bp1.y; P1.z += bp1.z; P1.w += bp1.w;
        float ss2 = wsum(P0.x * P0.x + P0.y * P0.y + P0.z * P0.z + P0.w * P0.w +
                         P1.x * P1.x + P1.y * P1.y + P1.z * P1.z + P1.w * P1.w);
        float inv2 = 1.f / fmaxf(sqrtf(ss2), 1e-12f);

        float4 M = (g < 4) ? P0 : P1;
        bool own = (lane >> 3) == (g & 3);
        float m0 = M.x * inv2, m1 = M.y * inv2, m2 = M.z * inv2, m3 = M.w * inv2;
        float loc = own ? fmaxf(fmaxf(m0, m1), fmaxf(m2, m3)) : -1e30f;
        float mx = wmax(loc);
        float ex0 = 0.f, ex1 = 0.f, ex2 = 0.f, ex3 = 0.f;
        if (own) {
            ex0 = __expf(m0 - mx); ex1 = __expf(m1 - mx);
            ex2 = __expf(m2 - mx); ex3 = __expf(m3 - mx);
        }
        float s = wsum(ex0 + ex1 + ex2 + ex3);
        if (own) {
            float is = 1.f / s;
            *(float4*)(g_result + (size_t)n * 32 + (lane & 7) * 4) =
                make_float4(ex0 * is, ex1 * is, ex2 * is, ex3 * is);
        }
    }
}

// ---------------- K6: merged post (adj 512 | pool 128 | dup 48 blocks) -------
__global__ __launch_bounds__(256) void k_post(const int* __restrict__ batch, float* out) {
    __shared__ float shf[640];
    __shared__ int srange[2];
    int b = blockIdx.x;
    int t = threadIdx.x;

    if (b < 512) {
        // ---- adj_new = sum_edges outer(S[src], S[dst]) ----
        int bk = b & 63, split = b >> 6;
        int s0 = g_bk_off[bk];
        int s1 = (bk == 63) ? EE : g_bk_off[bk + 1];
        int len = s1 - s0;
        int per = (len + 7) / 8;
        int e0 = s0 + split * per;
        int e1 = min(e0 + per, s1);
        float (*Sa)[32] = (float(*)[32])shf;
        float (*Sb)[32] = (float(*)[32])(shf + 256);
        int i = t >> 3, j0 = (t & 7) * 4;
        float4 acc = make_float4(0.f, 0.f, 0.f, 0.f);
        for (int base = e0; base < e1; base += 8) {
            int ne = min(8, e1 - base);
            if ((t >> 5) < ne) {
                int e = base + (t >> 5);
                int l = t & 31;
                Sa[t >> 5][l] = g_result[(size_t)g_eb_src[e] * 32 + l];
                Sb[t >> 5][l] = g_result[(size_t)g_eb_dst[e] * 32 + l];
            }
            __syncthreads();
            for (int jj = 0; jj < ne; jj++) {
                float a = Sa[jj][i];
                float4 bv = *(const float4*)&Sb[jj][j0];
                acc.x += a * bv.x; acc.y += a * bv.y;
                acc.z += a * bv.z; acc.w += a * bv.w;
            }
            __syncthreads();
        }
        if (e0 < e1) {
            int gs = bk >> 3, gd = bk & 7;
            float* dst = out + (size_t)(gs * 32 + i) * 256 + gd * 32 + j0;
            atomicAdd(dst + 0, acc.x); atomicAdd(dst + 1, acc.y);
            atomicAdd(dst + 2, acc.z); atomicAdd(dst + 3, acc.w);
        }
    } else if (b < 640) {
        // ---- h = S^T E and G = S^T S (per graph) ----
        int pb = b - 512;
        int g = pb & 7, split = pb >> 3;
        float (*Ms)[160] = (float(*)[160])shf;
        if (t == 0) { srange[0] = lbound(batch, g); srange[1] = lbound(batch, g + 1); }
        __syncthreads();
        int n0 = srange[0], n1 = srange[1];
        int len = n1 - n0;
        int per = (len + 15) / 16;
        int m0 = n0 + split * per;
        int m1 = min(m0 + per, n1);
        int i = t >> 3, j0 = (t & 7) * 4;
        float4 acc[5];
        #pragma unroll
        for (int c = 0; c < 5; c++) acc[c] = make_float4(0.f, 0.f, 0.f, 0.f);
        for (int base = m0; base < m1; base += 4) {
            int nn = min(4, m1 - base);
            for (int idx = t; idx < nn * 160; idx += 256) {
                int j = idx / 160, c = idx % 160;
                int n = base + j;
                Ms[j][c] = (c < 128) ? g_embed[(size_t)n * 128 + c]
                                     : g_result[(size_t)n * 32 + (c - 128)];
            }
            __syncthreads();
            for (int jj = 0; jj < nn; jj++) {
                float a = Ms[jj][128 + i];
                #pragma unroll
                for (int c = 0; c < 5; c++) {
                    float4 v = *(const float4*)&Ms[jj][j0 + 32 * c];
                    acc[c].x += a * v.x; acc[c].y += a * v.y;
                    acc[c].z += a * v.z; acc[c].w += a * v.w;
                }
            }
            __syncthreads();
        }
        if (m0 < m1) {
            #pragma unroll
            for (int c = 0; c < 4; c++) {
                float* dst = out + 65536 + (size_t)(g * 32 + i) * 128 + j0 + 32 * c;
                atomicAdd(dst + 0, acc[c].x); atomicAdd(dst + 1, acc[c].y);
                atomicAdd(dst + 2, acc[c].z); atomicAdd(dst + 3, acc[c].w);
            }
            float* dg = g_G + (size_t)g * 1024 + i * 32 + j0;
            atomicAdd(dg + 0, acc[4].x); atomicAdd(dg + 1, acc[4].y);
            atomicAdd(dg + 2, acc[4].z); atomicAdd(dg + 3, acc[4].w);
        }
    } else {
        // ---- sum of squared edge multiplicities (exact, int) ----
        int n = (b - 640) * 256 + t;
        int cnt = 0;
        if (n < NN) {
            int o = g_off[n], L = g_deg[n];
            for (int ii = 0; ii < L; ii++) {
                int si = g_src_by_dst[o + ii];
                for (int jj = 0; jj < L; jj++) cnt += (g_src_by_dst[o + jj] == si);
            }
        }
        #pragma unroll
        for (int off = 16; off; off >>= 1) cnt += __shfl_xor_sync(0xffffffffu, cnt, off);
        if ((t & 31) == 0) atomicAdd(&g_sumA2, (unsigned int)cnt);
    }
}

// ---------------- K7: finalize losses ----------------
__global__ void k_final(float* out) {
    __shared__ float red[256];
    int t = threadIdx.x;
    float v = out[(size_t)t * 257];          // trace(adj_new)
    red[t] = v;
    __syncthreads();
    for (int s = 128; s; s >>= 1) { if (t < s) red[t] += red[t + s]; __syncthreads(); }
    float tr = red[0];
    __syncthreads();
    float gq = 0.f;                          // ||G||_F^2
    for (int i = t; i < 8192; i += 256) { float g = g_G[i]; gq += g * g; }
    red[t] = gq;
    __syncthreads();
    for (int s = 128; s; s >>= 1) { if (t < s) red[t] += red[t + s]; __syncthreads(); }
    if (t == 0) {
        float a2 = (float)g_sumA2;
        float val = a2 - 2.f * tr + red[0];
        out[98304] = sqrtf(fmaxf(val, 0.f)) / 150994944.0f;   // / N^2
        out[98305] = 12288.0f * logf(32.0f);
    }
}

// ---------------- launch ----------------
extern "C" void kernel_launch(void* const* d_in, const int* in_sizes, int n_in,
                              void* d_out, int out_size) {
    const float* x     = (const float*)d_in[0];
    const int*   ei    = (const int*)d_in[1];
    const int*   batch = (const int*)d_in[2];
    const float* Wembd = (const float*)d_in[3];
    const float* bembd = (const float*)d_in[4];
    const float* Wpool = (const float*)d_in[5];
    const float* bpool = (const float*)d_in[6];
    float* out = (float*)d_out;

    static_assert(SM_TOT * 4 == 72192, "smem layout");
    cudaFuncSetAttribute(k_megemm, cudaFuncAttributeMaxDynamicSharedMemorySize,
                         SM_TOT * 4);

    k_init<<<384, 256>>>(out);
    k_hist<<<96, 256>>>(ei, batch);
    k_scan<<<1, 1024>>>();
    k_scatter<<<192, 1024>>>(ei, batch);
    k_megemm<<<384, 256, SM_TOT * 4>>>(x, Wembd, Wpool, bembd, bpool, batch);
    k_post<<<688, 256>>>(batch, out);
    k_final<<<1, 256>>>(out);
}

// round 13
// speedup vs baseline: 1.6914x; 1.1611x over previous
#include <cuda_runtime.h>
#include <math.h>

#define NN 12288
#define EE 196608
#define FF 128

// ---------------- static device scratch ----------------
__device__ int   g_deg[NN];
__device__ int   g_off[NN];
__device__ int   g_cur[NN];
__device__ int   g_src_by_dst[EE];
__device__ int   g_bk_cnt[64];
__device__ int   g_bk_off[64];
__device__ int   g_bk_cur[64];
__device__ int   g_eb_src[EE];
__device__ int   g_eb_dst[EE];
__device__ float g_agg[NN * FF];
__device__ float g_embed[NN * FF];
__device__ float g_result[NN * 32];
__device__ float g_G[8 * 32 * 32];
__device__ unsigned int g_sumA2;

// ---------------- helpers ----------------
__device__ __forceinline__ float wsum(float v) {
    #pragma unroll
    for (int o = 16; o; o >>= 1) v += __shfl_xor_sync(0xffffffffu, v, o);
    return v;
}
__device__ __forceinline__ float wmax(float v) {
    #pragma unroll
    for (int o = 16; o; o >>= 1) v = fmaxf(v, __shfl_xor_sync(0xffffffffu, v, o));
    return v;
}
__device__ __forceinline__ int lbound(const int* b, int v) {
    int lo = 0, hi = NN;
    while (lo < hi) { int m = (lo + hi) >> 1; if (b[m] < v) lo = m + 1; else hi = m; }
    return lo;
}
__device__ __forceinline__ void ffma2(unsigned long long &c, unsigned long long a,
                                      unsigned long long b) {
    asm("fma.rn.f32x2 %0, %1, %2, %0;" : "+l"(c) : "l"(a), "l"(b));
}
__device__ __forceinline__ unsigned long long pkdup(float a) {
    unsigned long long r;
    asm("mov.b64 %0, {%1, %1};" : "=l"(r) : "f"(a));
    return r;
}
__device__ __forceinline__ float2 upk(unsigned long long v) {
    float2 f;
    asm("mov.b64 {%0, %1}, %2;" : "=f"(f.x), "=f"(f.y) : "l"(v));
    return f;
}

// ---------------- K1: zero init ----------------
__global__ void k_init(float* out) {
    int i = blockIdx.x * 256 + threadIdx.x;
    if (i < 98304) out[i] = 0.f;            // adj_new (65536) + h (32768)
    if (i < NN) g_deg[i] = 0;
    if (i < 64) g_bk_cnt[i] = 0;
    if (i < 8192) g_G[i] = 0.f;
    if (i == 0) g_sumA2 = 0u;
}

// ---------------- K2: histograms (shared-mem aggregated) ----------------
__global__ __launch_bounds__(256) void k_hist(const int* __restrict__ ei,
                                              const int* __restrict__ batch) {
    __shared__ int h[64];
    int t = threadIdx.x;
    if (t < 64) h[t] = 0;
    __syncthreads();
    for (int i = blockIdx.x * 256 + t; i < EE; i += gridDim.x * 256) {
        int s = ei[i], d = ei[EE + i];
        atomicAdd(&g_deg[d], 1);
        atomicAdd(&h[batch[s] * 8 + batch[d]], 1);
    }
    __syncthreads();
    if (t < 64 && h[t]) atomicAdd(&g_bk_cnt[t], h[t]);
}

// ---------------- K3: exclusive scan (shfl-based) ----------------
__global__ void k_scan() {
    __shared__ int wsums[32];
    int t = threadIdx.x, lane = t & 31, w = t >> 5;
    int base = t * 12;
    int loc[12]; int s = 0;
    #pragma unroll
    for (int i = 0; i < 12; i++) { loc[i] = s; s += g_deg[base + i]; }
    int v = s;
    #pragma unroll
    for (int o = 1; o < 32; o <<= 1) {
        int u = __shfl_up_sync(0xffffffffu, v, o);
        if (lane >= o) v += u;
    }
    if (lane == 31) wsums[w] = v;
    __syncthreads();
    if (w == 0) {
        int u = wsums[lane];
        #pragma unroll
        for (int o = 1; o < 32; o <<= 1) {
            int z = __shfl_up_sync(0xffffffffu, u, o);
            if (lane >= o) u += z;
        }
        wsums[lane] = u;
    }
    __syncthreads();
    int pre = (v - s) + (w ? wsums[w - 1] : 0);
    #pragma unroll
    for (int i = 0; i < 12; i++) {
        int o = pre + loc[i];
        g_off[base + i] = o;
        g_cur[base + i] = o;
    }
    if (t == 0) {
        int acc = 0;
        for (int k = 0; k < 64; k++) {
            g_bk_off[k] = acc; g_bk_cur[k] = acc; acc += g_bk_cnt[k];
        }
    }
}

// ---------------- K4: scatter (block-local bucket ranking) ----------------
__global__ __launch_bounds__(1024) void k_scatter(const int* __restrict__ ei,
                                                  const int* __restrict__ batch) {
    __shared__ int cnt[64];
    __shared__ int base[64];
    int t = threadIdx.x;
    if (t < 64) cnt[t] = 0;
    __syncthreads();
    int i = blockIdx.x * 1024 + t;          // EE == 192 * 1024 exactly
    int s = ei[i], d = ei[EE + i];
    int key = batch[s] * 8 + batch[d];
    int rank = atomicAdd(&cnt[key], 1);
    int p = atomicAdd(&g_cur[d], 1);
    g_src_by_dst[p] = s;
    __syncthreads();
    if (t < 64) base[t] = cnt[t] ? atomicAdd(&g_bk_cur[t], cnt[t]) : 0;
    __syncthreads();
    int q = base[key] + rank;
    g_eb_src[q] = s;
    g_eb_dst[q] = d;
}

// ---------------- K5: mean aggregation (warp per dst node, high occupancy) ---
__global__ __launch_bounds__(256) void k_agg(const float* __restrict__ x) {
    int t = threadIdx.x, w = t >> 5, lane = t & 31;
    int n = blockIdx.x * 8 + w;
    int e0 = g_off[n], deg = g_deg[n];
    float4 a0 = make_float4(0.f, 0.f, 0.f, 0.f);
    float4 a1 = a0, a2 = a0, a3 = a0;
    for (int b0 = 0; b0 < deg; b0 += 32) {
        int rem = deg - b0;
        int m = rem < 32 ? rem : 32;
        int idx = (lane < m) ? g_src_by_dst[e0 + b0 + lane] : 0;
        int j = 0;
        for (; j + 4 <= m; j += 4) {
            int s0 = __shfl_sync(0xffffffffu, idx, j);
            int s1 = __shfl_sync(0xffffffffu, idx, j + 1);
            int s2 = __shfl_sync(0xffffffffu, idx, j + 2);
            int s3 = __shfl_sync(0xffffffffu, idx, j + 3);
            float4 v0 = *(const float4*)(x + (size_t)s0 * FF + lane * 4);
            float4 v1 = *(const float4*)(x + (size_t)s1 * FF + lane * 4);
            float4 v2 = *(const float4*)(x + (size_t)s2 * FF + lane * 4);
            float4 v3 = *(const float4*)(x + (size_t)s3 * FF + lane * 4);
            a0.x += v0.x; a0.y += v0.y; a0.z += v0.z; a0.w += v0.w;
            a1.x += v1.x; a1.y += v1.y; a1.z += v1.z; a1.w += v1.w;
            a2.x += v2.x; a2.y += v2.y; a2.z += v2.z; a2.w += v2.w;
            a3.x += v3.x; a3.y += v3.y; a3.z += v3.z; a3.w += v3.w;
        }
        for (; j < m; j++) {
            int sN = __shfl_sync(0xffffffffu, idx, j);
            float4 v = *(const float4*)(x + (size_t)sN * FF + lane * 4);
            a0.x += v.x; a0.y += v.y; a0.z += v.z; a0.w += v.w;
        }
    }
    float inv = 1.f / fmaxf((float)deg, 1.f);
    float4 r;
    r.x = (a0.x + a1.x + a2.x + a3.x) * inv;
    r.y = (a0.y + a1.y + a2.y + a3.y) * inv;
    r.z = (a0.z + a1.z + a2.z + a3.z) * inv;
    r.w = (a0.w + a1.w + a2.w + a3.w) * inv;
    *(float4*)(g_agg + (size_t)n * FF + lane * 4) = r;
}

// ---------------- K6: GEMM + epilogue (BK=32, gather removed) ----------------
// 32 rows/block, 256 threads (8 warps); warp w owns rows w*4..w*4+3.
// smem layout (floats): As[32*36] | Bs[32*384]
#define SM_AS   0
#define SM_BS   (32 * 36)
#define SM_TOT  (32 * 36 + 32 * 384)

__global__ __launch_bounds__(256, 2) void k_megemm(
    const float* __restrict__ x,
    const float* __restrict__ Wembd, const float* __restrict__ Wpool,
    const float* __restrict__ bembd, const float* __restrict__ bpool,
    const int* __restrict__ batch)
{
    extern __shared__ float sm[];
    float* As = sm + SM_AS;       // [32][36] transposed A chunk
    float* Bs = sm + SM_BS;       // [32][384] weight chunk
    int t = threadIdx.x, lane = t & 31, w = t >> 5;
    int row0 = blockIdx.x * 32;

    unsigned long long acc[4][3][2];
    #pragma unroll
    for (int r = 0; r < 4; r++)
        #pragma unroll
        for (int c = 0; c < 3; c++) { acc[r][c][0] = 0ull; acc[r][c][1] = 0ull; }

    int rb = t >> 3, c0 = (t & 7) * 4;      // B staging: row rb, cols c0+32j
    int r_a = t & 31, kq_a = (t >> 5) * 4;  // A staging mapping

    for (int c = 0; c < 8; c++) {
        int kc = c * 32;
        if (c) __syncthreads();             // prior compute done reading Bs/As
        {   // stage B chunk: 32 rows x 384 cols, interleaved 32-float strides
            const float* we = Wembd + (size_t)(kc + rb) * 128;
            const float* wp = Wpool + (size_t)(kc + rb) * 256 - 128;
            float* brow = Bs + rb * 384;
            #pragma unroll
            for (int j = 0; j < 12; j++) {
                int col = c0 + 32 * j;
                float4 v = (col < 128) ? *(const float4*)(we + col)
                                       : *(const float4*)(wp + col);
                *(float4*)(brow + col) = v;
            }
        }
        {   // stage A chunk transposed (x for c<4, agg for c>=4)
            const float* Asrc = (c < 4) ? x : g_agg;
            int kk = kc & 127;
            float4 v = *(const float4*)(Asrc + (size_t)(row0 + r_a) * FF + kk + kq_a);
            As[(kq_a + 0) * 36 + r_a] = v.x;
            As[(kq_a + 1) * 36 + r_a] = v.y;
            As[(kq_a + 2) * 36 + r_a] = v.z;
            As[(kq_a + 3) * 36 + r_a] = v.w;
        }
        __syncthreads();
        #pragma unroll
        for (int k = 0; k < 32; k++) {
            float4 a4 = *(const float4*)(As + k * 36 + w * 4); // warp-broadcast
            unsigned long long a0 = pkdup(a4.x), a1 = pkdup(a4.y);
            unsigned long long a2 = pkdup(a4.z), a3 = pkdup(a4.w);
            #pragma unroll
            for (int cc = 0; cc < 3; cc++) {
                ulonglong2 b = *(const ulonglong2*)(Bs + k * 384 + cc * 128 + lane * 4);
                ffma2(acc[0][cc][0], a0, b.x); ffma2(acc[0][cc][1], a0, b.y);
                ffma2(acc[1][cc][0], a1, b.x); ffma2(acc[1][cc][1], a1, b.y);
                ffma2(acc[2][cc][0], a2, b.x); ffma2(acc[2][cc][1], a2, b.y);
                ffma2(acc[3][cc][0], a3, b.x); ffma2(acc[3][cc][1], a3, b.y);
            }
        }
    }

    // ---- epilogue (bias, norms, block softmax) ----
    float4 be  = *(const float4*)(bembd + lane * 4);
    float4 bp0 = *(const float4*)(bpool + lane * 4);
    float4 bp1 = *(const float4*)(bpool + 128 + lane * 4);
    #pragma unroll
    for (int r = 0; r < 4; r++) {
        int n = row0 + w * 4 + r;
        int g = batch[n];
        float2 e0 = upk(acc[r][0][0]), e1 = upk(acc[r][0][1]);
        float4 v = make_float4(e0.x + be.x, e0.y + be.y, e1.x + be.z, e1.y + be.w);
        float ss = wsum(v.x * v.x + v.y * v.y + v.z * v.z + v.w * v.w);
        float inv = 1.f / fmaxf(sqrtf(ss), 1e-12f);
        *(float4*)(g_embed + (size_t)n * FF + lane * 4) =
            make_float4(v.x * inv, v.y * inv, v.z * inv, v.w * inv);

        float2 q0 = upk(acc[r][1][0]), q1 = upk(acc[r][1][1]);
        float2 q2 = upk(acc[r][2][0]), q3 = upk(acc[r][2][1]);
        float4 P0 = make_float4(q0.x + bp0.x, q0.y + bp0.y, q1.x + bp0.z, q1.y + bp0.w);
        float4 P1 = make_float4(q2.x + bp1.x, q2.y + bp1.y, q3.x + bp1.z, q3.y + bp1.w);
        float ss2 = wsum(P0.x * P0.x + P0.y * P0.y + P0.z * P0.z + P0.w * P0.w +
                         P1.x * P1.x + P1.y * P1.y + P1.z * P1.z + P1.w * P1.w);
        float inv2 = 1.f / fmaxf(sqrtf(ss2), 1e-12f);

        float4 M = (g < 4) ? P0 : P1;
        bool own = (lane >> 3) == (g & 3);
        float m0 = M.x * inv2, m1 = M.y * inv2, m2 = M.z * inv2, m3 = M.w * inv2;
        float loc = own ? fmaxf(fmaxf(m0, m1), fmaxf(m2, m3)) : -1e30f;
        float mx = wmax(loc);
        float ex0 = 0.f, ex1 = 0.f, ex2 = 0.f, ex3 = 0.f;
        if (own) {
            ex0 = __expf(m0 - mx); ex1 = __expf(m1 - mx);
            ex2 = __expf(m2 - mx); ex3 = __expf(m3 - mx);
        }
        float s = wsum(ex0 + ex1 + ex2 + ex3);
        if (own) {
            float is = 1.f / s;
            *(float4*)(g_result + (size_t)n * 32 + (lane & 7) * 4) =
                make_float4(ex0 * is, ex1 * is, ex2 * is, ex3 * is);
        }
    }
}

// ---------------- K7: merged post (adj 512 | pool 128 | dup 48 blocks) -------
__global__ __launch_bounds__(256) void k_post(const int* __restrict__ batch, float* out) {
    __shared__ float shf[1024];
    __shared__ int srange[2];
    int b = blockIdx.x;
    int t = threadIdx.x;

    if (b < 512) {
        // ---- adj_new = sum_edges outer(S[src], S[dst]), 16-edge tiles ----
        int bk = b & 63, split = b >> 6;
        int s0 = g_bk_off[bk];
        int s1 = (bk == 63) ? EE : g_bk_off[bk + 1];
        int len = s1 - s0;
        int per = (len + 7) / 8;
        int e0 = s0 + split * per;
        int e1 = min(e0 + per, s1);
        float (*Sa)[32] = (float(*)[32])shf;
        float (*Sb)[32] = (float(*)[32])(shf + 512);
        int el = t >> 4, q = t & 15;
        int i = t >> 3, j0 = (t & 7) * 4;
        float4 acc = make_float4(0.f, 0.f, 0.f, 0.f);
        for (int base = e0; base < e1; base += 16) {
            int ne = min(16, e1 - base);
            if (el < ne) {
                int e = base + el;
                if (q < 8)
                    *(float4*)&Sa[el][q * 4] =
                        *(const float4*)(g_result + (size_t)g_eb_src[e] * 32 + q * 4);
                else
                    *(float4*)&Sb[el][(q - 8) * 4] =
                        *(const float4*)(g_result + (size_t)g_eb_dst[e] * 32 + (q - 8) * 4);
            }
            __syncthreads();
            for (int jj = 0; jj < ne; jj++) {
                float a = Sa[jj][i];
                float4 bv = *(const float4*)&Sb[jj][j0];
                acc.x += a * bv.x; acc.y += a * bv.y;
                acc.z += a * bv.z; acc.w += a * bv.w;
            }
            __syncthreads();
        }
        if (e0 < e1) {
            int gs = bk >> 3, gd = bk & 7;
            float* dst = out + (size_t)(gs * 32 + i) * 256 + gd * 32 + j0;
            atomicAdd(dst + 0, acc.x); atomicAdd(dst + 1, acc.y);
            atomicAdd(dst + 2, acc.z); atomicAdd(dst + 3, acc.w);
        }
    } else if (b < 640) {
        // ---- h = S^T E and G = S^T S (per graph) ----
        int pb = b - 512;
        int g = pb & 7, split = pb >> 3;
        float (*Ms)[160] = (float(*)[160])shf;
        if (t == 0) { srange[0] = lbound(batch, g); srange[1] = lbound(batch, g + 1); }
        __syncthreads();
        int n0 = srange[0], n1 = srange[1];
        int len = n1 - n0;
        int per = (len + 15) / 16;
        int m0 = n0 + split * per;
        int m1 = min(m0 + per, n1);
        int i = t >> 3, j0 = (t & 7) * 4;
        float4 acc[5];
        #pragma unroll
        for (int c = 0; c < 5; c++) acc[c] = make_float4(0.f, 0.f, 0.f, 0.f);
        for (int base = m0; base < m1; base += 4) {
            int nn = min(4, m1 - base);
            for (int idx = t; idx < nn * 160; idx += 256) {
                int j = idx / 160, c = idx % 160;
                int n = base + j;
                Ms[j][c] = (c < 128) ? g_embed[(size_t)n * 128 + c]
                                     : g_result[(size_t)n * 32 + (c - 128)];
            }
            __syncthreads();
            for (int jj = 0; jj < nn; jj++) {
                float a = Ms[jj][128 + i];
                #pragma unroll
                for (int c = 0; c < 5; c++) {
                    float4 v = *(const float4*)&Ms[jj][j0 + 32 * c];
                    acc[c].x += a * v.x; acc[c].y += a * v.y;
                    acc[c].z += a * v.z; acc[c].w += a * v.w;
                }
            }
            __syncthreads();
        }
        if (m0 < m1) {
            #pragma unroll
            for (int c = 0; c < 4; c++) {
                float* dst = out + 65536 + (size_t)(g * 32 + i) * 128 + j0 + 32 * c;
                atomicAdd(dst + 0, acc[c].x); atomicAdd(dst + 1, acc[c].y);
                atomicAdd(dst + 2, acc[c].z); atomicAdd(dst + 3, acc[c].w);
            }
            float* dg = g_G + (size_t)g * 1024 + i * 32 + j0;
            atomicAdd(dg + 0, acc[4].x); atomicAdd(dg + 1, acc[4].y);
            atomicAdd(dg + 2, acc[4].z); atomicAdd(dg + 3, acc[4].w);
        }
    } else {
        // ---- sum of squared edge multiplicities (exact, int) ----
        int n = (b - 640) * 256 + t;
        int cnt = 0;
        if (n < NN) {
            int o = g_off[n], L = g_deg[n];
            for (int ii = 0; ii < L; ii++) {
                int si = g_src_by_dst[o + ii];
                for (int jj = 0; jj < L; jj++) cnt += (g_src_by_dst[o + jj] == si);
            }
        }
        #pragma unroll
        for (int off = 16; off; off >>= 1) cnt += __shfl_xor_sync(0xffffffffu, cnt, off);
        if ((t & 31) == 0) atomicAdd(&g_sumA2, (unsigned int)cnt);
    }
}

// ---------------- K8: finalize losses ----------------
__global__ void k_final(float* out) {
    __shared__ float red[256];
    int t = threadIdx.x;
    float v = out[(size_t)t * 257];          // trace(adj_new)
    red[t] = v;
    __syncthreads();
    for (int s = 128; s; s >>= 1) { if (t < s) red[t] += red[t + s]; __syncthreads(); }
    float tr = red[0];
    __syncthreads();
    float gq = 0.f;                          // ||G||_F^2
    for (int i = t; i < 8192; i += 256) { float g = g_G[i]; gq += g * g; }
    red[t] = gq;
    __syncthreads();
    for (int s = 128; s; s >>= 1) { if (t < s) red[t] += red[t + s]; __syncthreads(); }
    if (t == 0) {
        float a2 = (float)g_sumA2;
        float val = a2 - 2.f * tr + red[0];
        out[98304] = sqrtf(fmaxf(val, 0.f)) / 150994944.0f;   // / N^2
        out[98305] = 12288.0f * logf(32.0f);
    }
}

// ---------------- launch ----------------
extern "C" void kernel_launch(void* const* d_in, const int* in_sizes, int n_in,
                              void* d_out, int out_size) {
    const float* x     = (const float*)d_in[0];
    const int*   ei    = (const int*)d_in[1];
    const int*   batch = (const int*)d_in[2];
    const float* Wembd = (const float*)d_in[3];
    const float* bembd = (const float*)d_in[4];
    const float* Wpool = (const float*)d_in[5];
    const float* bpool = (const float*)d_in[6];
    float* out = (float*)d_out;

    static_assert(SM_TOT * 4 == 53760, "smem layout");
    cudaFuncSetAttribute(k_megemm, cudaFuncAttributeMaxDynamicSharedMemorySize,
                         SM_TOT * 4);

    k_init<<<384, 256>>>(out);
    k_hist<<<96, 256>>>(ei, batch);
    k_scan<<<1, 1024>>>();
    k_scatter<<<192, 1024>>>(ei, batch);
    k_agg<<<1536, 256>>>(x);
    k_megemm<<<384, 256, SM_TOT * 4>>>(x, Wembd, Wpool, bembd, bpool, batch);
    k_post<<<688, 256>>>(batch, out);
    k_final<<<1, 256>>>(out);
}